// round 12
// baseline (speedup 1.0000x reference)
#include <cuda_runtime.h>
#include <math.h>

#define B    128
#define C1   16
#define L0   719
#define L1   688
#define L3   171
#define CM   32
#define L9   174
#define CI   160
#define LI   171
#define LU   170
#define EPSL 1e-6f
#define LOGEPS  (-13.815511f)
#define LOG1PE  (9.9999905e-07f)

// ---------------- scratch ----------------
__device__ float  g_conv1[B*C1*L1];
__device__ double g_bns[C1*B*2];
__device__ float  g_xmiu[B*CM*L3];
__device__ float  g_h4[B*32*L9];
__device__ float  g_x1[B*40*LU];
__device__ float  g_x2[B*12*LU];
__device__ float  g_fc1o[B*12*1024];
__device__ float  g_fc2o[B*12*256];
__device__ float  g_wn_and2[20*CI*2];
__device__ float  g_wn_or2 [20*CI*2];
__device__ float  g_wn_and [6*200*2];
__device__ float  g_wn_or  [6*200*2];
__device__ float  g_s1_and[6];
__device__ float  g_s1_or[6];

static inline int cdiv(int a, int b) { return (a + b - 1) / b; }

__device__ __forceinline__ float sigfast(float z) {
    return __fdividef(1.0f, 1.0f + __expf(-z));
}
__device__ __forceinline__ int binof(float wv) {
    return (wv >= 0.8f) ? 4 : (wv >= 0.6f) ? 3 : (wv >= 0.4f) ? 2 : (wv >= 0.2f) ? 1 : 0;
}

// ---------------- conv1 + BN partial stats ----------------
__global__ void k_conv1(const float* __restrict__ x, const float* __restrict__ w) {
    int c = blockIdx.x, b = blockIdx.y;
    int tid = threadIdx.x;
    double ls = 0.0, ls2 = 0.0;
    if (tid < L1 / 4) {
        int t = tid * 4;
        const float* xr = x + b * L0 + t;
        const float* wr = w + c * 32;
        float s0 = 0.f, s1 = 0.f, s2 = 0.f, s3 = 0.f;
        float x0 = xr[0], x1v = xr[1], x2v = xr[2];
#pragma unroll
        for (int k = 0; k < 32; k++) {
            float xn = xr[k + 3];
            float wv = __ldg(wr + k);
            s0 = fmaf(x0, wv, s0);
            s1 = fmaf(x1v, wv, s1);
            s2 = fmaf(x2v, wv, s2);
            s3 = fmaf(xn, wv, s3);
            x0 = x1v; x1v = x2v; x2v = xn;
        }
        float* out = &g_conv1[(b * C1 + c) * L1 + t];
        out[0] = s0; out[1] = s1; out[2] = s2; out[3] = s3;
        ls = (double)s0 + (double)s1 + (double)s2 + (double)s3;
        ls2 = (double)s0*s0 + (double)s1*s1 + (double)s2*s2 + (double)s3*s3;
    }
    __shared__ double sh[256], sh2[256];
    sh[tid] = ls; sh2[tid] = ls2;
    __syncthreads();
    for (int st = 128; st > 0; st >>= 1) {
        if (tid < st) { sh[tid] += sh[tid + st]; sh2[tid] += sh2[tid + st]; }
        __syncthreads();
    }
    if (tid == 0) {
        g_bns[(c * B + b) * 2 + 0] = sh[0];
        g_bns[(c * B + b) * 2 + 1] = sh2[0];
    }
}

// ---------------- fused bnfin + bn + relu + pool + miu + pool ----------------
__global__ void k_front(const float* __restrict__ gg, const float* __restrict__ bb,
                        const float* __restrict__ ap, const float* __restrict__ bp,
                        const float* __restrict__ an, const float* __restrict__ bn) {
    int c = blockIdx.x, b = blockIdx.y;
    int tid = threadIdx.x;
    __shared__ double rs[4], rs2[4];
    __shared__ float ssc, ssh;
    if (tid < 128) {
        double s = g_bns[(c * B + tid) * 2 + 0];
        double q = g_bns[(c * B + tid) * 2 + 1];
#pragma unroll
        for (int o = 16; o > 0; o >>= 1) {
            s += __shfl_down_sync(0xffffffff, s, o);
            q += __shfl_down_sync(0xffffffff, q, o);
        }
        if ((tid & 31) == 0) { rs[tid >> 5] = s; rs2[tid >> 5] = q; }
    }
    __syncthreads();
    if (tid == 0) {
        double s = rs[0] + rs[1] + rs[2] + rs[3];
        double q = rs2[0] + rs2[1] + rs2[2] + rs2[3];
        double n = (double)(B * L1);
        double mean = s / n;
        double var = q / n - mean * mean;
        float inv = rsqrtf((float)var + 1e-5f);
        float sc = gg[c] * inv;
        ssc = sc;
        ssh = bb[c] - (float)mean * sc;
    }
    __syncthreads();
    if (tid >= L3) return;
    int l = tid;
    const float* cr = &g_conv1[(b * C1 + c) * L1 + 4 * l];
    float sc = ssc, sh = ssh;
    float a[7];
#pragma unroll
    for (int i = 0; i < 7; i++) a[i] = fmaxf(0.f, fmaf(cr[i], sc, sh));
    float xf0 = fmaxf(fmaxf(a[0], a[1]), a[2]);
    float xf1 = fmaxf(fmaxf(a[2], a[3]), a[4]);
    float xf2 = fmaxf(fmaxf(a[4], a[5]), a[6]);
    float a_p = ap[c], b_p = bp[c], a_n = an[c], b_n = bn[c];
    float mp = fmaxf(fmaxf(sigfast(a_p * (xf0 - b_p)), sigfast(a_p * (xf1 - b_p))),
                     sigfast(a_p * (xf2 - b_p)));
    float mn = fmaxf(fmaxf(sigfast(-a_n * (xf0 - b_n)), sigfast(-a_n * (xf1 - b_n))),
                     sigfast(-a_n * (xf2 - b_n)));
    g_xmiu[(b * CM + c) * L3 + l] = mp;
    g_xmiu[(b * CM + 16 + c) * L3 + l] = mn;
}

// ---------------- entire autoencoder in one kernel (512 threads / batch) ----------------
// smem floats: sW 6144 | sA 5709 | sB 11115 (91.9KB)
#define AE_NTH 512
__global__ void k_ae_all(const float* __restrict__ xmiu,
                         const float* __restrict__ w1, const float* __restrict__ b1,
                         const float* __restrict__ w2, const float* __restrict__ b2,
                         const float* __restrict__ w3, const float* __restrict__ b3,
                         const float* __restrict__ w4, const float* __restrict__ b4,
                         float* __restrict__ h4g) {
    extern __shared__ float sm[];
    float* sW = sm;
    float* sA = sm + 6144;
    float* sB = sm + 6144 + 5709;
    const int OFF2 = 8192;
    int b = blockIdx.x, tid = threadIdx.x;

    // S0: W1 + x staging (rows 0..172, stride 33)
    for (int i = tid; i < 6144; i += AE_NTH) {
        int oc = i / 96, r = i % 96, ic = r / 3, kw = r % 3;
        sW[(kw * 32 + ic) * 64 + oc] = w1[i];
    }
    for (int i = tid; i < 173 * 32; i += AE_NTH) {
        int r = i / 32, ic = i % 32, l = r - 1;
        sA[r * 33 + ic] = (l >= 0 && l < L3) ? xmiu[(b * 32 + ic) * L3 + l] : 0.f;
    }
    __syncthreads();

    // S1: conv1(k3,pad1)+tanh -> T1 in sB (171 rows, stride 65); TM=6, single pass (16*29=464)
    for (int it = tid; it < 16 * 29; it += AE_NTH) {
        int og = it % 16, lg = it / 16, l0 = lg * 6;
        float acc[6][4] = {};
#pragma unroll 4
        for (int ic = 0; ic < 32; ic++) {
            float a[8];
#pragma unroll
            for (int r = 0; r < 8; r++) a[r] = sA[min(l0 + r, 172) * 33 + ic];
#pragma unroll
            for (int kw = 0; kw < 3; kw++) {
                float4 wv = *reinterpret_cast<const float4*>(&sW[(kw * 32 + ic) * 64 + og * 4]);
#pragma unroll
                for (int i = 0; i < 6; i++) {
                    float av = a[i + kw];
                    acc[i][0] = fmaf(av, wv.x, acc[i][0]);
                    acc[i][1] = fmaf(av, wv.y, acc[i][1]);
                    acc[i][2] = fmaf(av, wv.z, acc[i][2]);
                    acc[i][3] = fmaf(av, wv.w, acc[i][3]);
                }
            }
        }
#pragma unroll
        for (int i = 0; i < 6; i++) {
            int l = l0 + i;
            if (l < L3)
#pragma unroll
                for (int j = 0; j < 4; j++)
                    sB[l * 65 + og * 4 + j] = tanhf(acc[i][j] + __ldg(b1 + og * 4 + j));
        }
    }
    __syncthreads();

    // S2: W2 + pool(3,2) T1 -> h1 in sA (87 rows incl pads, stride 65)
    for (int i = tid; i < 6144; i += AE_NTH) {
        int oc = i / 192, r = i % 192, ic = r / 3, kw = r % 3;
        sW[(kw * 64 + ic) * 32 + oc] = w2[i];
    }
    for (int i = tid; i < 87 * 64; i += AE_NTH) {
        int r = i / 64, ic = i % 64, p = r - 1;
        float v = 0.f;
        if (p >= 0 && p < 85) {
            const float* t1 = &sB[(2 * p) * 65 + ic];
            v = fmaxf(fmaxf(t1[0], t1[65]), t1[130]);
        }
        sA[r * 65 + ic] = v;
    }
    __syncthreads();

    // S3: conv2(k3,pad1)+relu -> T2 in sB rows 0..84 (stride 33); TM=3, float2 weights (16*29=464)
    for (int it = tid; it < 16 * 29; it += AE_NTH) {
        int og = it % 16, pg = it / 16, p0 = pg * 3;
        float acc[3][2] = {};
#pragma unroll 4
        for (int ic = 0; ic < 64; ic++) {
            float a[5];
#pragma unroll
            for (int r = 0; r < 5; r++) a[r] = sA[min(p0 + r, 86) * 65 + ic];
#pragma unroll
            for (int kw = 0; kw < 3; kw++) {
                float2 wv = *reinterpret_cast<const float2*>(&sW[(kw * 64 + ic) * 32 + og * 2]);
#pragma unroll
                for (int i = 0; i < 3; i++) {
                    float av = a[i + kw];
                    acc[i][0] = fmaf(av, wv.x, acc[i][0]);
                    acc[i][1] = fmaf(av, wv.y, acc[i][1]);
                }
            }
        }
#pragma unroll
        for (int i = 0; i < 3; i++) {
            int p = p0 + i;
            if (p < 85)
#pragma unroll
                for (int j = 0; j < 2; j++)
                    sB[p * 33 + og * 2 + j] = fmaxf(0.f, acc[i][j] + __ldg(b2 + og * 2 + j));
        }
    }
    __syncthreads();

    // S4: W3 + pool(3,2) T2 -> h2 at sB[OFF2] (42 rows, stride 33)
    for (int i = tid; i < 6144; i += AE_NTH) {
        int oc = i / 96, r = i % 96, ic = r / 3, kw = r % 3;
        sW[(kw * 32 + ic) * 64 + oc] = w3[i];
    }
    for (int i = tid; i < 42 * 32; i += AE_NTH) {
        int j = i / 32, ic = i % 32;
        const float* t2 = &sB[(2 * j) * 33 + ic];
        sB[OFF2 + j * 33 + ic] = fmaxf(fmaxf(t2[0], t2[33]), t2[66]);
    }
    __syncthreads();

    // S5: up2(h2) -> conv3(k3,pad2)+tanh -> h3 in sA (86 rows, stride 65); TM=3 (16*29=464)
    for (int it = tid; it < 16 * 29; it += AE_NTH) {
        int og = it % 16, tg = it / 16, t0 = tg * 3;
        float acc[3][4] = {};
#pragma unroll 4
        for (int ic = 0; ic < 32; ic++) {
            float a[5];
#pragma unroll
            for (int r = 0; r < 5; r++) {
                int u = t0 - 2 + r;
                float av = 0.f;
                if (u >= 0 && u < 84) {
                    int j = u >> 1;
                    int ja, jb; float wa, wb;
                    if (u & 1) { ja = j; jb = (j < 41) ? j + 1 : 41; wa = 0.75f; wb = 0.25f; }
                    else       { ja = (j > 0) ? j - 1 : 0; jb = j;  wa = 0.25f; wb = 0.75f; }
                    av = wa * sB[OFF2 + ja * 33 + ic] + wb * sB[OFF2 + jb * 33 + ic];
                }
                a[r] = av;
            }
#pragma unroll
            for (int kw = 0; kw < 3; kw++) {
                float4 wv = *reinterpret_cast<const float4*>(&sW[(kw * 32 + ic) * 64 + og * 4]);
#pragma unroll
                for (int i = 0; i < 3; i++) {
                    float av = a[i + kw];
                    acc[i][0] = fmaf(av, wv.x, acc[i][0]);
                    acc[i][1] = fmaf(av, wv.y, acc[i][1]);
                    acc[i][2] = fmaf(av, wv.z, acc[i][2]);
                    acc[i][3] = fmaf(av, wv.w, acc[i][3]);
                }
            }
        }
#pragma unroll
        for (int i = 0; i < 3; i++) {
            int t = t0 + i;
            if (t < 86)
#pragma unroll
                for (int j = 0; j < 4; j++)
                    sA[t * 65 + og * 4 + j] = tanhf(acc[i][j] + __ldg(b3 + og * 4 + j));
        }
    }
    __syncthreads();

    // S6: W4
    for (int i = tid; i < 6144; i += AE_NTH) {
        int oc = i / 192, r = i % 192, ic = r / 3, kw = r % 3;
        sW[(kw * 64 + ic) * 32 + oc] = w4[i];
    }
    __syncthreads();

    // S7: up2(h3) -> conv4(k3,pad2)+sigmoid -> h4 GLOBAL channel-first; TM=3 (8*58=464)
    for (int it = tid; it < 8 * 58; it += AE_NTH) {
        int og = it % 8, tg = it / 8, t0 = tg * 3;
        float acc[3][4] = {};
#pragma unroll 4
        for (int ic = 0; ic < 64; ic++) {
            float a[5];
#pragma unroll
            for (int r = 0; r < 5; r++) {
                int u = t0 - 2 + r;
                float av = 0.f;
                if (u >= 0 && u < 172) {
                    int j = u >> 1;
                    int ja, jb; float wa, wb;
                    if (u & 1) { ja = j; jb = (j < 85) ? j + 1 : 85; wa = 0.75f; wb = 0.25f; }
                    else       { ja = (j > 0) ? j - 1 : 0; jb = j;  wa = 0.25f; wb = 0.75f; }
                    av = wa * sA[ja * 65 + ic] + wb * sA[jb * 65 + ic];
                }
                a[r] = av;
            }
#pragma unroll
            for (int kw = 0; kw < 3; kw++) {
                float4 wv = *reinterpret_cast<const float4*>(&sW[(kw * 64 + ic) * 32 + og * 4]);
#pragma unroll
                for (int i = 0; i < 3; i++) {
                    float av = a[i + kw];
                    acc[i][0] = fmaf(av, wv.x, acc[i][0]);
                    acc[i][1] = fmaf(av, wv.y, acc[i][1]);
                    acc[i][2] = fmaf(av, wv.z, acc[i][2]);
                    acc[i][3] = fmaf(av, wv.w, acc[i][3]);
                }
            }
        }
#pragma unroll
        for (int i = 0; i < 3; i++) {
            int t = t0 + i;
            if (t < L9)
#pragma unroll
                for (int j = 0; j < 4; j++)
                    h4g[(b * 32 + og * 4 + j) * L9 + t] =
                        sigfast(acc[i][j] + __ldg(b4 + og * 4 + j));
        }
    }
}

// ---------------- softmax of logic weights + odd-tap sums ----------------
__global__ void k_softmax_all(const float* __restrict__ and2_w, const float* __restrict__ or2_w,
                              const float* __restrict__ and_w, const float* __restrict__ or_w) {
    int blk = blockIdx.x;
    const float* src; float* dst; int sz, o; float* s1dst = nullptr;
    if (blk < 20)      { src = and2_w; dst = g_wn_and2; sz = 320; o = blk; }
    else if (blk < 40) { src = or2_w;  dst = g_wn_or2;  sz = 320; o = blk - 20; }
    else if (blk < 46) { src = and_w;  dst = g_wn_and;  sz = 400; o = blk - 40; s1dst = g_s1_and; }
    else               { src = or_w;   dst = g_wn_or;   sz = 400; o = blk - 46; s1dst = g_s1_or; }
    const float* row = src + o * sz;
    int tid = threadIdx.x;
    __shared__ float red[64];
    float mx = -INFINITY;
    for (int i = tid; i < sz; i += 64) mx = fmaxf(mx, row[i]);
    red[tid] = mx; __syncthreads();
    for (int s = 32; s > 0; s >>= 1) { if (tid < s) red[tid] = fmaxf(red[tid], red[tid + s]); __syncthreads(); }
    mx = red[0]; __syncthreads();
    float sm = 0.f;
    for (int i = tid; i < sz; i += 64) sm += expf(row[i] - mx);
    red[tid] = sm; __syncthreads();
    for (int s = 32; s > 0; s >>= 1) { if (tid < s) red[tid] += red[tid + s]; __syncthreads(); }
    sm = red[0]; __syncthreads();
    float sodd = 0.f;
    for (int i = tid; i < sz; i += 64) {
        float v = expf(row[i] - mx) / sm;
        dst[o * sz + i] = v;
        if (i & 1) sodd += v;
    }
    if (s1dst) {
        red[tid] = sodd; __syncthreads();
        for (int s = 32; s > 0; s >>= 1) { if (tid < s) red[tid] += red[tid + s]; __syncthreads(); }
        if (tid == 0) s1dst[o] = red[0];
    }
}

// ---------------- logic layer 1 ----------------
__global__ void k_logic1() {
    __shared__ float2 sw2[20 * CI];
    int tid = threadIdx.x;
    int type = blockIdx.y;
    const float2* wsrc = reinterpret_cast<const float2*>(type == 0 ? g_wn_and2 : g_wn_or2);
    for (int i = tid; i < 20 * CI; i += 128) sw2[i] = wsrc[i];
    __syncthreads();
    int idx = blockIdx.x * 128 + tid;
    if (idx >= B * LU) return;
    int t = idx % LU, b = idx / LU;
    float base = (type == 0) ? LOGEPS : LOG1PE;
    float acc[20];
#pragma unroll
    for (int o = 0; o < 20; o++) acc[o] = base;
    for (int c = 0; c < 32; c++) {
        const float* h4p = &g_h4[(b * 32 + c) * L9 + t];
        float h0 = h4p[0], h1 = h4p[1], h2 = h4p[2], h3 = h4p[3], h4v = h4p[4];
        float wv0 = fmaxf(fmaxf(h0, h1), fmaxf(h2, h3));
        float wv1 = fmaxf(fmaxf(h1, h2), fmaxf(h3, h4v));
        const float* xmp = &g_xmiu[(b * 32 + c) * L3 + t];
        float p0 = wv0 * xmp[0], p1 = wv1 * xmp[1];
        int ch0 = binof(wv0) * 32 + c;
        int ch1 = binof(wv1) * 32 + c;
        float d0, d1;
        if (type == 0) {
            d0 = __logf(p0 + EPSL) - LOGEPS;
            d1 = __logf(p1 + EPSL) - LOGEPS;
        } else {
            d0 = __logf(1.0f - p0 + EPSL) - LOG1PE;
            d1 = __logf(1.0f - p1 + EPSL) - LOG1PE;
        }
#pragma unroll
        for (int o = 0; o < 20; o++) {
            acc[o] = fmaf(sw2[o * CI + ch0].x, d0, acc[o]);
            acc[o] = fmaf(sw2[o * CI + ch1].y, d1, acc[o]);
        }
    }
    float* x1 = &g_x1[(b * 40 + (type == 0 ? 0 : 20)) * LU + t];
    if (type == 0) {
#pragma unroll
        for (int o = 0; o < 20; o++) x1[o * LU] = fmaxf(0.f, __expf(acc[o]));
    } else {
#pragma unroll
        for (int o = 0; o < 20; o++) x1[o * LU] = fmaxf(0.f, 1.0f - __expf(acc[o]));
    }
}

// ---------------- logic layer 2 ----------------
__global__ void k_logic2() {
    __shared__ float2 swa2[6 * 200];
    __shared__ float2 swo2[6 * 200];
    int tid = threadIdx.x;
    const float2* wa = reinterpret_cast<const float2*>(g_wn_and);
    const float2* wo = reinterpret_cast<const float2*>(g_wn_or);
    for (int i = tid; i < 6 * 200; i += 128) { swa2[i] = wa[i]; swo2[i] = wo[i]; }
    __syncthreads();
    int idx = blockIdx.x * 128 + tid;
    if (idx >= B * LU) return;
    int t = idx % LU, b = idx / LU;
    bool hasL = (t > 0);
    float sa[6], so[6];
#pragma unroll
    for (int o = 0; o < 6; o++) {
        float fa = hasL ? 1.0f : g_s1_and[o];
        float fo = hasL ? 1.0f : g_s1_or[o];
        sa[o] = LOGEPS * fa;
        so[o] = LOG1PE * fo;
    }
    const float* xp = &g_x1[b * 40 * LU + t];
    for (int c = 0; c < 40; c++) {
        float v1 = xp[c * LU];
        float cv1 = fminf(fmaxf(v1, 0.f), 1.f);
        float d1p = __logf(cv1 + EPSL) - LOGEPS;
        float d1q = __logf(1.0f - cv1 + EPSL) - LOG1PE;
        float d0p = 0.f, d0q = 0.f;
        if (hasL) {
            float v0 = xp[c * LU - 1];
            float cv0 = fminf(fmaxf(v0, 0.f), 1.f);
            d0p = __logf(cv0 + EPSL) - LOGEPS;
            d0q = __logf(1.0f - cv0 + EPSL) - LOG1PE;
        }
#pragma unroll
        for (int o = 0; o < 6; o++) {
            float2 a2 = swa2[o * 200 + c];
            float2 o2 = swo2[o * 200 + c];
            sa[o] = fmaf(a2.y, d1p, sa[o]);
            so[o] = fmaf(o2.y, d1q, so[o]);
            if (hasL) {
                sa[o] = fmaf(a2.x, d0p, sa[o]);
                so[o] = fmaf(o2.x, d0q, so[o]);
            }
        }
    }
    for (int c = 0; c < 32; c++) {
        const float* h4p = &g_h4[(b * 32 + c) * L9 + t];
        const float* xmp = &g_xmiu[(b * 32 + c) * L3 + t];
        float h0 = h4p[0], h1 = h4p[1], h2 = h4p[2], h3 = h4p[3], h4v = h4p[4];
        float wv0 = fmaxf(fmaxf(h0, h1), fmaxf(h2, h3));
        float wv1 = fmaxf(fmaxf(h1, h2), fmaxf(h3, h4v));
        float p_0 = wv0 * xmp[0], p_1 = wv1 * xmp[1];
        int k0 = binof(wv0), k1 = binof(wv1);
        if (k0 == k1) {
            int ch = 40 + k0 * 32 + c;
            float u = fminf(p_0, p_1);
            float dp = __logf(u + EPSL) - LOGEPS;
            float dq = __logf(1.0f - u + EPSL) - LOG1PE;
#pragma unroll
            for (int o = 0; o < 6; o++) {
                sa[o] = fmaf(swa2[o * 200 + ch].y, dp, sa[o]);
                so[o] = fmaf(swo2[o * 200 + ch].y, dq, so[o]);
            }
        }
        if (hasL) {
            float hm1 = h4p[-1];
            float wvm = fmaxf(fmaxf(hm1, h0), fmaxf(h1, h2));
            float p_m = wvm * xmp[-1];
            int km = binof(wvm);
            if (km == k0) {
                int ch = 40 + km * 32 + c;
                float u = fminf(p_m, p_0);
                float dp = __logf(u + EPSL) - LOGEPS;
                float dq = __logf(1.0f - u + EPSL) - LOG1PE;
#pragma unroll
                for (int o = 0; o < 6; o++) {
                    sa[o] = fmaf(swa2[o * 200 + ch].x, dp, sa[o]);
                    so[o] = fmaf(swo2[o * 200 + ch].x, dq, so[o]);
                }
            }
        }
    }
#pragma unroll
    for (int o = 0; o < 6; o++) {
        g_x2[(b * 12 + o) * LU + t] = fmaxf(0.f, __expf(sa[o]));
        g_x2[(b * 12 + 6 + o) * LU + t] = fmaxf(0.f, 1.0f - __expf(so[o]));
    }
}

// ---------------- FC GEMM (64x64x16, 4x4, 256 thr) — fc1 ----------------
__global__ void k_gemm64(const float* __restrict__ A, const float* __restrict__ W,
                         const float* __restrict__ bias, float* __restrict__ C,
                         int M, int N, int K, int relu) {
    __shared__ float As[16][68];
    __shared__ float Bs[16][68];
    int tid = threadIdx.x;
    int tx = tid % 16, ty = tid / 16;
    int m0 = blockIdx.y * 64, n0 = blockIdx.x * 64;
    float acc[4][4] = {};
    for (int k0 = 0; k0 < K; k0 += 16) {
        int gk = k0 + tx;
        bool kv = (gk < K);
#pragma unroll
        for (int i = 0; i < 4; i++) {
            int r = ty + i * 16;
            int gm = m0 + r;
            As[tx][r] = (kv && gm < M) ? A[gm * K + gk] : 0.f;
            int gn = n0 + r;
            Bs[tx][r] = (kv && gn < N) ? W[gn * K + gk] : 0.f;
        }
        __syncthreads();
#pragma unroll
        for (int kk = 0; kk < 16; kk++) {
            float4 a = *reinterpret_cast<const float4*>(&As[kk][ty * 4]);
            float4 bq = *reinterpret_cast<const float4*>(&Bs[kk][tx * 4]);
            float av[4] = {a.x, a.y, a.z, a.w};
            float bv[4] = {bq.x, bq.y, bq.z, bq.w};
#pragma unroll
            for (int i = 0; i < 4; i++)
#pragma unroll
                for (int j = 0; j < 4; j++)
                    acc[i][j] = fmaf(av[i], bv[j], acc[i][j]);
        }
        __syncthreads();
    }
#pragma unroll
    for (int i = 0; i < 4; i++) {
        int gm = m0 + ty * 4 + i;
        if (gm >= M) continue;
#pragma unroll
        for (int j = 0; j < 4; j++) {
            int gn = n0 + tx * 4 + j;
            if (gn >= N) continue;
            float v = acc[i][j] + bias[gn];
            if (relu) v = fmaxf(v, 0.f);
            C[gm * N + gn] = v;
        }
    }
}

// ---------------- FC GEMM (64x64x16, 4x2, 512 thr) — fc2 (same tile, 2x warps) ----------------
__global__ void k_gemm64w(const float* __restrict__ A, const float* __restrict__ W,
                          const float* __restrict__ bias, float* __restrict__ C,
                          int M, int N, int K, int relu) {
    __shared__ float As[16][68];
    __shared__ float Bs[16][68];
    int tid = threadIdx.x;          // 512
    int tx = tid % 32, ty = tid / 32;  // tx: 32 col-pairs, ty: 16 row-quads
    int m0 = blockIdx.y * 64, n0 = blockIdx.x * 64;
    float acc[4][2] = {};
    for (int k0 = 0; k0 < K; k0 += 16) {
        for (int i = tid; i < 64 * 16; i += 512) {
            int kk = i % 16, r = i / 16;
            int gm = m0 + r, gk = k0 + kk;
            As[kk][r] = (gm < M && gk < K) ? A[gm * K + gk] : 0.f;
        }
        for (int i = tid; i < 64 * 16; i += 512) {
            int kk = i % 16, r = i / 16;
            int gn = n0 + r, gk = k0 + kk;
            Bs[kk][r] = (gn < N && gk < K) ? W[gn * K + gk] : 0.f;
        }
        __syncthreads();
#pragma unroll
        for (int kk = 0; kk < 16; kk++) {
            float4 a = *reinterpret_cast<const float4*>(&As[kk][ty * 4]);
            float2 b2 = *reinterpret_cast<const float2*>(&Bs[kk][tx * 2]);
            float av[4] = {a.x, a.y, a.z, a.w};
#pragma unroll
            for (int i = 0; i < 4; i++) {
                acc[i][0] = fmaf(av[i], b2.x, acc[i][0]);
                acc[i][1] = fmaf(av[i], b2.y, acc[i][1]);
            }
        }
        __syncthreads();
    }
#pragma unroll
    for (int i = 0; i < 4; i++) {
        int gm = m0 + ty * 4 + i;
        if (gm >= M) continue;
#pragma unroll
        for (int j = 0; j < 2; j++) {
            int gn = n0 + tx * 2 + j;
            if (gn >= N) continue;
            float v = acc[i][j] + bias[gn];
            if (relu) v = fmaxf(v, 0.f);
            C[gm * N + gn] = v;
        }
    }
}

__global__ void k_fc3(const float* __restrict__ A, const float* __restrict__ W,
                      const float* __restrict__ bias, float* __restrict__ C) {
    int idx = blockIdx.x * blockDim.x + threadIdx.x;
    if (idx >= B * 12 * 10) return;
    int m = idx / 10, n = idx % 10;
    float s = bias[n];
    const float* a = A + m * 256;
    const float* w = W + n * 256;
#pragma unroll 8
    for (int k = 0; k < 256; k++) s = fmaf(a[k], __ldg(w + k), s);
    C[idx] = s;
}

// ---------------- launcher ----------------

extern "C" void kernel_launch(void* const* d_in, const int* in_sizes, int n_in,
                              void* d_out, int out_size) {
    const float* x      = (const float*)d_in[0];
    const float* wave_w = (const float*)d_in[1];
    const float* bn_g   = (const float*)d_in[2];
    const float* bn_b   = (const float*)d_in[3];
    const float* miu_ap = (const float*)d_in[4];
    const float* miu_bp = (const float*)d_in[5];
    const float* miu_an = (const float*)d_in[6];
    const float* miu_bn = (const float*)d_in[7];
    const float* ae_w1  = (const float*)d_in[8];
    const float* ae_b1  = (const float*)d_in[9];
    const float* ae_w2  = (const float*)d_in[10];
    const float* ae_b2  = (const float*)d_in[11];
    const float* ae_w3  = (const float*)d_in[12];
    const float* ae_b3  = (const float*)d_in[13];
    const float* ae_w4  = (const float*)d_in[14];
    const float* ae_b4  = (const float*)d_in[15];
    const float* and2_w = (const float*)d_in[16];
    const float* or2_w  = (const float*)d_in[17];
    const float* and_w  = (const float*)d_in[18];
    const float* or_w   = (const float*)d_in[19];
    const float* fc1_w  = (const float*)d_in[20];
    const float* fc1_b  = (const float*)d_in[21];
    const float* fc2_w  = (const float*)d_in[22];
    const float* fc2_b  = (const float*)d_in[23];
    const float* fc3_w  = (const float*)d_in[24];
    const float* fc3_b  = (const float*)d_in[25];
    float* out = (float*)d_out;

    float *pxmiu, *ph4, *px2, *pf1, *pf2;
    cudaGetSymbolAddress((void**)&pxmiu, g_xmiu);
    cudaGetSymbolAddress((void**)&ph4, g_h4);
    cudaGetSymbolAddress((void**)&px2, g_x2);
    cudaGetSymbolAddress((void**)&pf1, g_fc1o);
    cudaGetSymbolAddress((void**)&pf2, g_fc2o);

    const int AE_SMEM = (6144 + 5709 + 11115) * 4;
    cudaFuncSetAttribute(k_ae_all, cudaFuncAttributeMaxDynamicSharedMemorySize, AE_SMEM);

    k_softmax_all<<<52, 64>>>(and2_w, or2_w, and_w, or_w);
    k_conv1<<<dim3(C1, B), 256>>>(x, wave_w);
    k_front<<<dim3(C1, B), 192>>>(bn_g, bn_b, miu_ap, miu_bp, miu_an, miu_bn);
    k_ae_all<<<B, AE_NTH, AE_SMEM>>>(pxmiu, ae_w1, ae_b1, ae_w2, ae_b2,
                                     ae_w3, ae_b3, ae_w4, ae_b4, ph4);
    k_logic1<<<dim3(cdiv(B * LU, 128), 2), 128>>>();
    k_logic2<<<cdiv(B * LU, 128), 128>>>();
    k_gemm64<<<dim3(1024 / 64, (B * 12) / 64), 256>>>(px2, fc1_w, fc1_b, pf1, B * 12, 1024, LU, 1);
    k_gemm64w<<<dim3(256 / 64, (B * 12) / 64), 512>>>(pf1, fc2_w, fc2_b, pf2, B * 12, 256, 1024, 1);
    k_fc3<<<cdiv(B * 12 * 10, 256), 256>>>(pf2, fc3_w, fc3_b, out);

    (void)in_sizes; (void)n_in; (void)out_size;
}

// round 13
// speedup vs baseline: 1.2449x; 1.2449x over previous
#include <cuda_runtime.h>
#include <math.h>

#define B    128
#define C1   16
#define L0   719
#define L1   688
#define L3   171
#define CM   32
#define L9   174
#define CI   160
#define LI   171
#define LU   170
#define EPSL 1e-6f
#define LOGEPS  (-13.815511f)
#define LOG1PE  (9.9999905e-07f)

// ---------------- scratch ----------------
__device__ float  g_conv1[B*C1*L1];
__device__ double g_bns[C1*B*2];
__device__ float  g_xmiu[B*CM*L3];
__device__ float  g_h4[B*32*L9];
__device__ float  g_x1[B*40*LU];
__device__ float  g_x2[B*12*LU];
__device__ float  g_fc1o[B*12*1024];
__device__ float  g_fc2o[B*12*256];
__device__ float  g_wn_and2[20*CI*2];
__device__ float  g_wn_or2 [20*CI*2];
__device__ float  g_wn_and [6*200*2];
__device__ float  g_wn_or  [6*200*2];
__device__ float  g_s1_and[6];
__device__ float  g_s1_or[6];

static inline int cdiv(int a, int b) { return (a + b - 1) / b; }

__device__ __forceinline__ float sigfast(float z) {
    return __fdividef(1.0f, 1.0f + __expf(-z));
}
__device__ __forceinline__ int binof(float wv) {
    return (wv >= 0.8f) ? 4 : (wv >= 0.6f) ? 3 : (wv >= 0.4f) ? 2 : (wv >= 0.2f) ? 1 : 0;
}

// ---------------- conv1 + BN partial stats ----------------
__global__ void k_conv1(const float* __restrict__ x, const float* __restrict__ w) {
    int c = blockIdx.x, b = blockIdx.y;
    int tid = threadIdx.x;
    double ls = 0.0, ls2 = 0.0;
    if (tid < L1 / 4) {
        int t = tid * 4;
        const float* xr = x + b * L0 + t;
        const float* wr = w + c * 32;
        float s0 = 0.f, s1 = 0.f, s2 = 0.f, s3 = 0.f;
        float x0 = xr[0], x1v = xr[1], x2v = xr[2];
#pragma unroll
        for (int k = 0; k < 32; k++) {
            float xn = xr[k + 3];
            float wv = __ldg(wr + k);
            s0 = fmaf(x0, wv, s0);
            s1 = fmaf(x1v, wv, s1);
            s2 = fmaf(x2v, wv, s2);
            s3 = fmaf(xn, wv, s3);
            x0 = x1v; x1v = x2v; x2v = xn;
        }
        float* out = &g_conv1[(b * C1 + c) * L1 + t];
        out[0] = s0; out[1] = s1; out[2] = s2; out[3] = s3;
        ls = (double)s0 + (double)s1 + (double)s2 + (double)s3;
        ls2 = (double)s0*s0 + (double)s1*s1 + (double)s2*s2 + (double)s3*s3;
    }
    __shared__ double sh[256], sh2[256];
    sh[tid] = ls; sh2[tid] = ls2;
    __syncthreads();
    for (int st = 128; st > 0; st >>= 1) {
        if (tid < st) { sh[tid] += sh[tid + st]; sh2[tid] += sh2[tid + st]; }
        __syncthreads();
    }
    if (tid == 0) {
        g_bns[(c * B + b) * 2 + 0] = sh[0];
        g_bns[(c * B + b) * 2 + 1] = sh2[0];
    }
}

// ---------------- fused bnfin + bn + relu + pool + miu + pool ----------------
__global__ void k_front(const float* __restrict__ gg, const float* __restrict__ bb,
                        const float* __restrict__ ap, const float* __restrict__ bp,
                        const float* __restrict__ an, const float* __restrict__ bn) {
    int c = blockIdx.x, b = blockIdx.y;
    int tid = threadIdx.x;
    __shared__ double rs[4], rs2[4];
    __shared__ float ssc, ssh;
    if (tid < 128) {
        double s = g_bns[(c * B + tid) * 2 + 0];
        double q = g_bns[(c * B + tid) * 2 + 1];
#pragma unroll
        for (int o = 16; o > 0; o >>= 1) {
            s += __shfl_down_sync(0xffffffff, s, o);
            q += __shfl_down_sync(0xffffffff, q, o);
        }
        if ((tid & 31) == 0) { rs[tid >> 5] = s; rs2[tid >> 5] = q; }
    }
    __syncthreads();
    if (tid == 0) {
        double s = rs[0] + rs[1] + rs[2] + rs[3];
        double q = rs2[0] + rs2[1] + rs2[2] + rs2[3];
        double n = (double)(B * L1);
        double mean = s / n;
        double var = q / n - mean * mean;
        float inv = rsqrtf((float)var + 1e-5f);
        float sc = gg[c] * inv;
        ssc = sc;
        ssh = bb[c] - (float)mean * sc;
    }
    __syncthreads();
    if (tid >= L3) return;
    int l = tid;
    const float* cr = &g_conv1[(b * C1 + c) * L1 + 4 * l];
    float sc = ssc, sh = ssh;
    float a[7];
#pragma unroll
    for (int i = 0; i < 7; i++) a[i] = fmaxf(0.f, fmaf(cr[i], sc, sh));
    float xf0 = fmaxf(fmaxf(a[0], a[1]), a[2]);
    float xf1 = fmaxf(fmaxf(a[2], a[3]), a[4]);
    float xf2 = fmaxf(fmaxf(a[4], a[5]), a[6]);
    float a_p = ap[c], b_p = bp[c], a_n = an[c], b_n = bn[c];
    float mp = fmaxf(fmaxf(sigfast(a_p * (xf0 - b_p)), sigfast(a_p * (xf1 - b_p))),
                     sigfast(a_p * (xf2 - b_p)));
    float mn = fmaxf(fmaxf(sigfast(-a_n * (xf0 - b_n)), sigfast(-a_n * (xf1 - b_n))),
                     sigfast(-a_n * (xf2 - b_n)));
    g_xmiu[(b * CM + c) * L3 + l] = mp;
    g_xmiu[(b * CM + 16 + c) * L3 + l] = mn;
}

// ---------------- entire autoencoder in one kernel (512 threads / batch) ----------------
// smem floats: sW 6144 | sA 5709 | sB 11115 (91.9KB)
#define AE_NTH 512
__global__ void k_ae_all(const float* __restrict__ xmiu,
                         const float* __restrict__ w1, const float* __restrict__ b1,
                         const float* __restrict__ w2, const float* __restrict__ b2,
                         const float* __restrict__ w3, const float* __restrict__ b3,
                         const float* __restrict__ w4, const float* __restrict__ b4,
                         float* __restrict__ h4g) {
    extern __shared__ float sm[];
    float* sW = sm;
    float* sA = sm + 6144;
    float* sB = sm + 6144 + 5709;
    const int OFF2 = 8192;
    int b = blockIdx.x, tid = threadIdx.x;

    // S0: W1 + x staging (rows 0..172, stride 33)
    for (int i = tid; i < 6144; i += AE_NTH) {
        int oc = i / 96, r = i % 96, ic = r / 3, kw = r % 3;
        sW[(kw * 32 + ic) * 64 + oc] = w1[i];
    }
    for (int i = tid; i < 173 * 32; i += AE_NTH) {
        int r = i / 32, ic = i % 32, l = r - 1;
        sA[r * 33 + ic] = (l >= 0 && l < L3) ? xmiu[(b * 32 + ic) * L3 + l] : 0.f;
    }
    __syncthreads();

    // S1: conv1(k3,pad1)+tanh -> T1 in sB (171 rows, stride 65); TM=6 single pass (16*29=464)
    for (int it = tid; it < 16 * 29; it += AE_NTH) {
        int og = it % 16, lg = it / 16, l0 = lg * 6;
        float acc[6][4] = {};
#pragma unroll 4
        for (int ic = 0; ic < 32; ic++) {
            float a[8];
#pragma unroll
            for (int r = 0; r < 8; r++) a[r] = sA[min(l0 + r, 172) * 33 + ic];
#pragma unroll
            for (int kw = 0; kw < 3; kw++) {
                float4 wv = *reinterpret_cast<const float4*>(&sW[(kw * 32 + ic) * 64 + og * 4]);
#pragma unroll
                for (int i = 0; i < 6; i++) {
                    float av = a[i + kw];
                    acc[i][0] = fmaf(av, wv.x, acc[i][0]);
                    acc[i][1] = fmaf(av, wv.y, acc[i][1]);
                    acc[i][2] = fmaf(av, wv.z, acc[i][2]);
                    acc[i][3] = fmaf(av, wv.w, acc[i][3]);
                }
            }
        }
#pragma unroll
        for (int i = 0; i < 6; i++) {
            int l = l0 + i;
            if (l < L3)
#pragma unroll
                for (int j = 0; j < 4; j++)
                    sB[l * 65 + og * 4 + j] = tanhf(acc[i][j] + __ldg(b1 + og * 4 + j));
        }
    }
    __syncthreads();

    // S2: W2 + pool(3,2) T1 -> h1 in sA (87 rows incl pads, stride 65)
    for (int i = tid; i < 6144; i += AE_NTH) {
        int oc = i / 192, r = i % 192, ic = r / 3, kw = r % 3;
        sW[(kw * 64 + ic) * 32 + oc] = w2[i];
    }
    for (int i = tid; i < 87 * 64; i += AE_NTH) {
        int r = i / 64, ic = i % 64, p = r - 1;
        float v = 0.f;
        if (p >= 0 && p < 85) {
            const float* t1 = &sB[(2 * p) * 65 + ic];
            v = fmaxf(fmaxf(t1[0], t1[65]), t1[130]);
        }
        sA[r * 65 + ic] = v;
    }
    __syncthreads();

    // S3: conv2(k3,pad1)+relu -> T2 in sB rows 0..84 (stride 33); TM=4, float2 weights, act regs
    for (int it = tid; it < 16 * 22; it += AE_NTH) {
        int og = it % 16, pg = it / 16, p0 = pg * 4;
        float acc[4][2] = {};
#pragma unroll 4
        for (int ic = 0; ic < 64; ic++) {
            float a[6];
#pragma unroll
            for (int r = 0; r < 6; r++) a[r] = sA[min(p0 + r, 86) * 65 + ic];
#pragma unroll
            for (int kw = 0; kw < 3; kw++) {
                float2 wv = *reinterpret_cast<const float2*>(&sW[(kw * 64 + ic) * 32 + og * 2]);
#pragma unroll
                for (int i = 0; i < 4; i++) {
                    float av = a[i + kw];
                    acc[i][0] = fmaf(av, wv.x, acc[i][0]);
                    acc[i][1] = fmaf(av, wv.y, acc[i][1]);
                }
            }
        }
#pragma unroll
        for (int i = 0; i < 4; i++) {
            int p = p0 + i;
            if (p < 85)
#pragma unroll
                for (int j = 0; j < 2; j++)
                    sB[p * 33 + og * 2 + j] = fmaxf(0.f, acc[i][j] + __ldg(b2 + og * 2 + j));
        }
    }
    __syncthreads();

    // S4: W3 + pool(3,2) T2 -> h2 at sB[OFF2] (42 rows, stride 33)
    for (int i = tid; i < 6144; i += AE_NTH) {
        int oc = i / 96, r = i % 96, ic = r / 3, kw = r % 3;
        sW[(kw * 32 + ic) * 64 + oc] = w3[i];
    }
    for (int i = tid; i < 42 * 32; i += AE_NTH) {
        int j = i / 32, ic = i % 32;
        const float* t2 = &sB[(2 * j) * 33 + ic];
        sB[OFF2 + j * 33 + ic] = fmaxf(fmaxf(t2[0], t2[33]), t2[66]);
    }
    __syncthreads();

    // S5: up2(h2) -> conv3(k3,pad2)+tanh -> h3 in sA (86 rows, stride 65); TM=4, up-gathers hoisted
    for (int it = tid; it < 352; it += AE_NTH) {
        int og = it % 16, tg = it / 16, t0 = tg * 4;
        float acc[4][4] = {};
#pragma unroll 4
        for (int ic = 0; ic < 32; ic++) {
            float a[7];
#pragma unroll
            for (int r = 0; r < 7; r++) {
                int u = t0 - 2 + r;
                float av = 0.f;
                if (u >= 0 && u < 84) {
                    int j = u >> 1;
                    int ja, jb; float wa, wb;
                    if (u & 1) { ja = j; jb = (j < 41) ? j + 1 : 41; wa = 0.75f; wb = 0.25f; }
                    else       { ja = (j > 0) ? j - 1 : 0; jb = j;  wa = 0.25f; wb = 0.75f; }
                    av = wa * sB[OFF2 + ja * 33 + ic] + wb * sB[OFF2 + jb * 33 + ic];
                }
                a[r] = av;
            }
#pragma unroll
            for (int kw = 0; kw < 3; kw++) {
                float4 wv = *reinterpret_cast<const float4*>(&sW[(kw * 32 + ic) * 64 + og * 4]);
#pragma unroll
                for (int i = 0; i < 4; i++) {
                    float av = a[i + kw];
                    acc[i][0] = fmaf(av, wv.x, acc[i][0]);
                    acc[i][1] = fmaf(av, wv.y, acc[i][1]);
                    acc[i][2] = fmaf(av, wv.z, acc[i][2]);
                    acc[i][3] = fmaf(av, wv.w, acc[i][3]);
                }
            }
        }
#pragma unroll
        for (int i = 0; i < 4; i++) {
            int t = t0 + i;
            if (t < 86)
#pragma unroll
                for (int j = 0; j < 4; j++)
                    sA[t * 65 + og * 4 + j] = tanhf(acc[i][j] + __ldg(b3 + og * 4 + j));
        }
    }
    __syncthreads();

    // S6: W4
    for (int i = tid; i < 6144; i += AE_NTH) {
        int oc = i / 192, r = i % 192, ic = r / 3, kw = r % 3;
        sW[(kw * 64 + ic) * 32 + oc] = w4[i];
    }
    __syncthreads();

    // S7: up2(h3) -> conv4(k3,pad2)+sigmoid -> h4 GLOBAL channel-first; TM=4, up-gathers hoisted
    for (int it = tid; it < 352; it += AE_NTH) {
        int og = it % 8, tg = it / 8, t0 = tg * 4;
        float acc[4][4] = {};
#pragma unroll 4
        for (int ic = 0; ic < 64; ic++) {
            float a[7];
#pragma unroll
            for (int r = 0; r < 7; r++) {
                int u = t0 - 2 + r;
                float av = 0.f;
                if (u >= 0 && u < 172) {
                    int j = u >> 1;
                    int ja, jb; float wa, wb;
                    if (u & 1) { ja = j; jb = (j < 85) ? j + 1 : 85; wa = 0.75f; wb = 0.25f; }
                    else       { ja = (j > 0) ? j - 1 : 0; jb = j;  wa = 0.25f; wb = 0.75f; }
                    av = wa * sA[ja * 65 + ic] + wb * sA[jb * 65 + ic];
                }
                a[r] = av;
            }
#pragma unroll
            for (int kw = 0; kw < 3; kw++) {
                float4 wv = *reinterpret_cast<const float4*>(&sW[(kw * 64 + ic) * 32 + og * 4]);
#pragma unroll
                for (int i = 0; i < 4; i++) {
                    float av = a[i + kw];
                    acc[i][0] = fmaf(av, wv.x, acc[i][0]);
                    acc[i][1] = fmaf(av, wv.y, acc[i][1]);
                    acc[i][2] = fmaf(av, wv.z, acc[i][2]);
                    acc[i][3] = fmaf(av, wv.w, acc[i][3]);
                }
            }
        }
#pragma unroll
        for (int i = 0; i < 4; i++) {
            int t = t0 + i;
            if (t < L9)
#pragma unroll
                for (int j = 0; j < 4; j++)
                    h4g[(b * 32 + og * 4 + j) * L9 + t] =
                        sigfast(acc[i][j] + __ldg(b4 + og * 4 + j));
        }
    }
}

// ---------------- softmax of logic weights + odd-tap sums ----------------
__global__ void k_softmax_all(const float* __restrict__ and2_w, const float* __restrict__ or2_w,
                              const float* __restrict__ and_w, const float* __restrict__ or_w) {
    int blk = blockIdx.x;
    const float* src; float* dst; int sz, o; float* s1dst = nullptr;
    if (blk < 20)      { src = and2_w; dst = g_wn_and2; sz = 320; o = blk; }
    else if (blk < 40) { src = or2_w;  dst = g_wn_or2;  sz = 320; o = blk - 20; }
    else if (blk < 46) { src = and_w;  dst = g_wn_and;  sz = 400; o = blk - 40; s1dst = g_s1_and; }
    else               { src = or_w;   dst = g_wn_or;   sz = 400; o = blk - 46; s1dst = g_s1_or; }
    const float* row = src + o * sz;
    int tid = threadIdx.x;
    __shared__ float red[64];
    float mx = -INFINITY;
    for (int i = tid; i < sz; i += 64) mx = fmaxf(mx, row[i]);
    red[tid] = mx; __syncthreads();
    for (int s = 32; s > 0; s >>= 1) { if (tid < s) red[tid] = fmaxf(red[tid], red[tid + s]); __syncthreads(); }
    mx = red[0]; __syncthreads();
    float sm = 0.f;
    for (int i = tid; i < sz; i += 64) sm += expf(row[i] - mx);
    red[tid] = sm; __syncthreads();
    for (int s = 32; s > 0; s >>= 1) { if (tid < s) red[tid] += red[tid + s]; __syncthreads(); }
    sm = red[0]; __syncthreads();
    float sodd = 0.f;
    for (int i = tid; i < sz; i += 64) {
        float v = expf(row[i] - mx) / sm;
        dst[o * sz + i] = v;
        if (i & 1) sodd += v;
    }
    if (s1dst) {
        red[tid] = sodd; __syncthreads();
        for (int s = 32; s > 0; s >>= 1) { if (tid < s) red[tid] += red[tid + s]; __syncthreads(); }
        if (tid == 0) s1dst[o] = red[0];
    }
}

// ---------------- logic layer 1 ----------------
__global__ void k_logic1() {
    __shared__ float2 sw2[20 * CI];
    int tid = threadIdx.x;
    int type = blockIdx.y;
    const float2* wsrc = reinterpret_cast<const float2*>(type == 0 ? g_wn_and2 : g_wn_or2);
    for (int i = tid; i < 20 * CI; i += 128) sw2[i] = wsrc[i];
    __syncthreads();
    int idx = blockIdx.x * 128 + tid;
    if (idx >= B * LU) return;
    int t = idx % LU, b = idx / LU;
    float base = (type == 0) ? LOGEPS : LOG1PE;
    float acc[20];
#pragma unroll
    for (int o = 0; o < 20; o++) acc[o] = base;
    for (int c = 0; c < 32; c++) {
        const float* h4p = &g_h4[(b * 32 + c) * L9 + t];
        float h0 = h4p[0], h1 = h4p[1], h2 = h4p[2], h3 = h4p[3], h4v = h4p[4];
        float wv0 = fmaxf(fmaxf(h0, h1), fmaxf(h2, h3));
        float wv1 = fmaxf(fmaxf(h1, h2), fmaxf(h3, h4v));
        const float* xmp = &g_xmiu[(b * 32 + c) * L3 + t];
        float p0 = wv0 * xmp[0], p1 = wv1 * xmp[1];
        int ch0 = binof(wv0) * 32 + c;
        int ch1 = binof(wv1) * 32 + c;
        float d0, d1;
        if (type == 0) {
            d0 = __logf(p0 + EPSL) - LOGEPS;
            d1 = __logf(p1 + EPSL) - LOGEPS;
        } else {
            d0 = __logf(1.0f - p0 + EPSL) - LOG1PE;
            d1 = __logf(1.0f - p1 + EPSL) - LOG1PE;
        }
#pragma unroll
        for (int o = 0; o < 20; o++) {
            acc[o] = fmaf(sw2[o * CI + ch0].x, d0, acc[o]);
            acc[o] = fmaf(sw2[o * CI + ch1].y, d1, acc[o]);
        }
    }
    float* x1 = &g_x1[(b * 40 + (type == 0 ? 0 : 20)) * LU + t];
    if (type == 0) {
#pragma unroll
        for (int o = 0; o < 20; o++) x1[o * LU] = fmaxf(0.f, __expf(acc[o]));
    } else {
#pragma unroll
        for (int o = 0; o < 20; o++) x1[o * LU] = fmaxf(0.f, 1.0f - __expf(acc[o]));
    }
}

// ---------------- logic layer 2 ----------------
__global__ void k_logic2() {
    __shared__ float2 swa2[6 * 200];
    __shared__ float2 swo2[6 * 200];
    int tid = threadIdx.x;
    const float2* wa = reinterpret_cast<const float2*>(g_wn_and);
    const float2* wo = reinterpret_cast<const float2*>(g_wn_or);
    for (int i = tid; i < 6 * 200; i += 128) { swa2[i] = wa[i]; swo2[i] = wo[i]; }
    __syncthreads();
    int idx = blockIdx.x * 128 + tid;
    if (idx >= B * LU) return;
    int t = idx % LU, b = idx / LU;
    bool hasL = (t > 0);
    float sa[6], so[6];
#pragma unroll
    for (int o = 0; o < 6; o++) {
        float fa = hasL ? 1.0f : g_s1_and[o];
        float fo = hasL ? 1.0f : g_s1_or[o];
        sa[o] = LOGEPS * fa;
        so[o] = LOG1PE * fo;
    }
    const float* xp = &g_x1[b * 40 * LU + t];
    for (int c = 0; c < 40; c++) {
        float v1 = xp[c * LU];
        float cv1 = fminf(fmaxf(v1, 0.f), 1.f);
        float d1p = __logf(cv1 + EPSL) - LOGEPS;
        float d1q = __logf(1.0f - cv1 + EPSL) - LOG1PE;
        float d0p = 0.f, d0q = 0.f;
        if (hasL) {
            float v0 = xp[c * LU - 1];
            float cv0 = fminf(fmaxf(v0, 0.f), 1.f);
            d0p = __logf(cv0 + EPSL) - LOGEPS;
            d0q = __logf(1.0f - cv0 + EPSL) - LOG1PE;
        }
#pragma unroll
        for (int o = 0; o < 6; o++) {
            float2 a2 = swa2[o * 200 + c];
            float2 o2 = swo2[o * 200 + c];
            sa[o] = fmaf(a2.y, d1p, sa[o]);
            so[o] = fmaf(o2.y, d1q, so[o]);
            if (hasL) {
                sa[o] = fmaf(a2.x, d0p, sa[o]);
                so[o] = fmaf(o2.x, d0q, so[o]);
            }
        }
    }
    for (int c = 0; c < 32; c++) {
        const float* h4p = &g_h4[(b * 32 + c) * L9 + t];
        const float* xmp = &g_xmiu[(b * 32 + c) * L3 + t];
        float h0 = h4p[0], h1 = h4p[1], h2 = h4p[2], h3 = h4p[3], h4v = h4p[4];
        float wv0 = fmaxf(fmaxf(h0, h1), fmaxf(h2, h3));
        float wv1 = fmaxf(fmaxf(h1, h2), fmaxf(h3, h4v));
        float p_0 = wv0 * xmp[0], p_1 = wv1 * xmp[1];
        int k0 = binof(wv0), k1 = binof(wv1);
        if (k0 == k1) {
            int ch = 40 + k0 * 32 + c;
            float u = fminf(p_0, p_1);
            float dp = __logf(u + EPSL) - LOGEPS;
            float dq = __logf(1.0f - u + EPSL) - LOG1PE;
#pragma unroll
            for (int o = 0; o < 6; o++) {
                sa[o] = fmaf(swa2[o * 200 + ch].y, dp, sa[o]);
                so[o] = fmaf(swo2[o * 200 + ch].y, dq, so[o]);
            }
        }
        if (hasL) {
            float hm1 = h4p[-1];
            float wvm = fmaxf(fmaxf(hm1, h0), fmaxf(h1, h2));
            float p_m = wvm * xmp[-1];
            int km = binof(wvm);
            if (km == k0) {
                int ch = 40 + km * 32 + c;
                float u = fminf(p_m, p_0);
                float dp = __logf(u + EPSL) - LOGEPS;
                float dq = __logf(1.0f - u + EPSL) - LOG1PE;
#pragma unroll
                for (int o = 0; o < 6; o++) {
                    sa[o] = fmaf(swa2[o * 200 + ch].x, dp, sa[o]);
                    so[o] = fmaf(swo2[o * 200 + ch].x, dq, so[o]);
                }
            }
        }
    }
#pragma unroll
    for (int o = 0; o < 6; o++) {
        g_x2[(b * 12 + o) * LU + t] = fmaxf(0.f, __expf(sa[o]));
        g_x2[(b * 12 + 6 + o) * LU + t] = fmaxf(0.f, 1.0f - __expf(so[o]));
    }
}

// ---------------- FC GEMM (64x64x16, 4x4, 256 thr) ----------------
__global__ void k_gemm64(const float* __restrict__ A, const float* __restrict__ W,
                         const float* __restrict__ bias, float* __restrict__ C,
                         int M, int N, int K, int relu) {
    __shared__ float As[16][68];
    __shared__ float Bs[16][68];
    int tid = threadIdx.x;
    int tx = tid % 16, ty = tid / 16;
    int m0 = blockIdx.y * 64, n0 = blockIdx.x * 64;
    float acc[4][4] = {};
    for (int k0 = 0; k0 < K; k0 += 16) {
        int gk = k0 + tx;
        bool kv = (gk < K);
#pragma unroll
        for (int i = 0; i < 4; i++) {
            int r = ty + i * 16;
            int gm = m0 + r;
            As[tx][r] = (kv && gm < M) ? A[gm * K + gk] : 0.f;
            int gn = n0 + r;
            Bs[tx][r] = (kv && gn < N) ? W[gn * K + gk] : 0.f;
        }
        __syncthreads();
#pragma unroll
        for (int kk = 0; kk < 16; kk++) {
            float4 a = *reinterpret_cast<const float4*>(&As[kk][ty * 4]);
            float4 bq = *reinterpret_cast<const float4*>(&Bs[kk][tx * 4]);
            float av[4] = {a.x, a.y, a.z, a.w};
            float bv[4] = {bq.x, bq.y, bq.z, bq.w};
#pragma unroll
            for (int i = 0; i < 4; i++)
#pragma unroll
                for (int j = 0; j < 4; j++)
                    acc[i][j] = fmaf(av[i], bv[j], acc[i][j]);
        }
        __syncthreads();
    }
#pragma unroll
    for (int i = 0; i < 4; i++) {
        int gm = m0 + ty * 4 + i;
        if (gm >= M) continue;
#pragma unroll
        for (int j = 0; j < 4; j++) {
            int gn = n0 + tx * 4 + j;
            if (gn >= N) continue;
            float v = acc[i][j] + bias[gn];
            if (relu) v = fmaxf(v, 0.f);
            C[gm * N + gn] = v;
        }
    }
}

__global__ void k_fc3(const float* __restrict__ A, const float* __restrict__ W,
                      const float* __restrict__ bias, float* __restrict__ C) {
    int idx = blockIdx.x * blockDim.x + threadIdx.x;
    if (idx >= B * 12 * 10) return;
    int m = idx / 10, n = idx % 10;
    float s = bias[n];
    const float* a = A + m * 256;
    const float* w = W + n * 256;
#pragma unroll 8
    for (int k = 0; k < 256; k++) s = fmaf(a[k], __ldg(w + k), s);
    C[idx] = s;
}

// ---------------- launcher ----------------

extern "C" void kernel_launch(void* const* d_in, const int* in_sizes, int n_in,
                              void* d_out, int out_size) {
    const float* x      = (const float*)d_in[0];
    const float* wave_w = (const float*)d_in[1];
    const float* bn_g   = (const float*)d_in[2];
    const float* bn_b   = (const float*)d_in[3];
    const float* miu_ap = (const float*)d_in[4];
    const float* miu_bp = (const float*)d_in[5];
    const float* miu_an = (const float*)d_in[6];
    const float* miu_bn = (const float*)d_in[7];
    const float* ae_w1  = (const float*)d_in[8];
    const float* ae_b1  = (const float*)d_in[9];
    const float* ae_w2  = (const float*)d_in[10];
    const float* ae_b2  = (const float*)d_in[11];
    const float* ae_w3  = (const float*)d_in[12];
    const float* ae_b3  = (const float*)d_in[13];
    const float* ae_w4  = (const float*)d_in[14];
    const float* ae_b4  = (const float*)d_in[15];
    const float* and2_w = (const float*)d_in[16];
    const float* or2_w  = (const float*)d_in[17];
    const float* and_w  = (const float*)d_in[18];
    const float* or_w   = (const float*)d_in[19];
    const float* fc1_w  = (const float*)d_in[20];
    const float* fc1_b  = (const float*)d_in[21];
    const float* fc2_w  = (const float*)d_in[22];
    const float* fc2_b  = (const float*)d_in[23];
    const float* fc3_w  = (const float*)d_in[24];
    const float* fc3_b  = (const float*)d_in[25];
    float* out = (float*)d_out;

    float *pxmiu, *ph4, *px2, *pf1, *pf2;
    cudaGetSymbolAddress((void**)&pxmiu, g_xmiu);
    cudaGetSymbolAddress((void**)&ph4, g_h4);
    cudaGetSymbolAddress((void**)&px2, g_x2);
    cudaGetSymbolAddress((void**)&pf1, g_fc1o);
    cudaGetSymbolAddress((void**)&pf2, g_fc2o);

    const int AE_SMEM = (6144 + 5709 + 11115) * 4;
    cudaFuncSetAttribute(k_ae_all, cudaFuncAttributeMaxDynamicSharedMemorySize, AE_SMEM);

    k_softmax_all<<<52, 64>>>(and2_w, or2_w, and_w, or_w);
    k_conv1<<<dim3(C1, B), 256>>>(x, wave_w);
    k_front<<<dim3(C1, B), 192>>>(bn_g, bn_b, miu_ap, miu_bp, miu_an, miu_bn);
    k_ae_all<<<B, AE_NTH, AE_SMEM>>>(pxmiu, ae_w1, ae_b1, ae_w2, ae_b2,
                                     ae_w3, ae_b3, ae_w4, ae_b4, ph4);
    k_logic1<<<dim3(cdiv(B * LU, 128), 2), 128>>>();
    k_logic2<<<cdiv(B * LU, 128), 128>>>();
    k_gemm64<<<dim3(1024 / 64, (B * 12) / 64), 256>>>(px2, fc1_w, fc1_b, pf1, B * 12, 1024, LU, 1);
    k_gemm64<<<dim3(256 / 64, (B * 12) / 64), 256>>>(pf1, fc2_w, fc2_b, pf2, B * 12, 256, 1024, 1);
    k_fc3<<<cdiv(B * 12 * 10, 256), 256>>>(pf2, fc3_w, fc3_b, out);

    (void)in_sizes; (void)n_in; (void)out_size;
}

// round 14
// speedup vs baseline: 1.2854x; 1.0326x over previous
#include <cuda_runtime.h>
#include <math.h>

#define B    128
#define C1   16
#define L0   719
#define L1   688
#define L3   171
#define CM   32
#define L9   174
#define CI   160
#define LI   171
#define LU   170
#define EPSL 1e-6f
#define LOGEPS  (-13.815511f)
#define LOG1PE  (9.9999905e-07f)

// ---------------- scratch ----------------
__device__ float  g_conv1[B*C1*L1];
__device__ double g_bns[C1*B*2];
__device__ float  g_xmiu[B*CM*L3];
__device__ float  g_h4[B*32*L9];
__device__ float  g_x1[B*40*LU];
__device__ float  g_x2[B*12*LU];
__device__ float  g_fc1o[B*12*1024];
__device__ float  g_fc2p[2*B*12*256];   // K-split partials
__device__ float  g_wn_and2[20*CI*2];
__device__ float  g_wn_or2 [20*CI*2];
__device__ float  g_wn_and [6*200*2];
__device__ float  g_wn_or  [6*200*2];
__device__ float  g_s1_and[6];
__device__ float  g_s1_or[6];

static inline int cdiv(int a, int b) { return (a + b - 1) / b; }

__device__ __forceinline__ float sigfast(float z) {
    return __fdividef(1.0f, 1.0f + __expf(-z));
}
__device__ __forceinline__ int binof(float wv) {
    return (wv >= 0.8f) ? 4 : (wv >= 0.6f) ? 3 : (wv >= 0.4f) ? 2 : (wv >= 0.2f) ? 1 : 0;
}

// ---------------- conv1 + BN partial stats ----------------
__global__ void k_conv1(const float* __restrict__ x, const float* __restrict__ w) {
    int c = blockIdx.x, b = blockIdx.y;
    int tid = threadIdx.x;
    double ls = 0.0, ls2 = 0.0;
    if (tid < L1 / 4) {
        int t = tid * 4;
        const float* xr = x + b * L0 + t;
        const float* wr = w + c * 32;
        float s0 = 0.f, s1 = 0.f, s2 = 0.f, s3 = 0.f;
        float x0 = xr[0], x1v = xr[1], x2v = xr[2];
#pragma unroll
        for (int k = 0; k < 32; k++) {
            float xn = xr[k + 3];
            float wv = __ldg(wr + k);
            s0 = fmaf(x0, wv, s0);
            s1 = fmaf(x1v, wv, s1);
            s2 = fmaf(x2v, wv, s2);
            s3 = fmaf(xn, wv, s3);
            x0 = x1v; x1v = x2v; x2v = xn;
        }
        float* out = &g_conv1[(b * C1 + c) * L1 + t];
        out[0] = s0; out[1] = s1; out[2] = s2; out[3] = s3;
        ls = (double)s0 + (double)s1 + (double)s2 + (double)s3;
        ls2 = (double)s0*s0 + (double)s1*s1 + (double)s2*s2 + (double)s3*s3;
    }
    __shared__ double sh[256], sh2[256];
    sh[tid] = ls; sh2[tid] = ls2;
    __syncthreads();
    for (int st = 128; st > 0; st >>= 1) {
        if (tid < st) { sh[tid] += sh[tid + st]; sh2[tid] += sh2[tid + st]; }
        __syncthreads();
    }
    if (tid == 0) {
        g_bns[(c * B + b) * 2 + 0] = sh[0];
        g_bns[(c * B + b) * 2 + 1] = sh2[0];
    }
}

// ---------------- fused bnfin + bn + relu + pool + miu + pool ----------------
__global__ void k_front(const float* __restrict__ gg, const float* __restrict__ bb,
                        const float* __restrict__ ap, const float* __restrict__ bp,
                        const float* __restrict__ an, const float* __restrict__ bn) {
    int c = blockIdx.x, b = blockIdx.y;
    int tid = threadIdx.x;
    __shared__ double rs[4], rs2[4];
    __shared__ float ssc, ssh;
    if (tid < 128) {
        double s = g_bns[(c * B + tid) * 2 + 0];
        double q = g_bns[(c * B + tid) * 2 + 1];
#pragma unroll
        for (int o = 16; o > 0; o >>= 1) {
            s += __shfl_down_sync(0xffffffff, s, o);
            q += __shfl_down_sync(0xffffffff, q, o);
        }
        if ((tid & 31) == 0) { rs[tid >> 5] = s; rs2[tid >> 5] = q; }
    }
    __syncthreads();
    if (tid == 0) {
        double s = rs[0] + rs[1] + rs[2] + rs[3];
        double q = rs2[0] + rs2[1] + rs2[2] + rs2[3];
        double n = (double)(B * L1);
        double mean = s / n;
        double var = q / n - mean * mean;
        float inv = rsqrtf((float)var + 1e-5f);
        float sc = gg[c] * inv;
        ssc = sc;
        ssh = bb[c] - (float)mean * sc;
    }
    __syncthreads();
    if (tid >= L3) return;
    int l = tid;
    const float* cr = &g_conv1[(b * C1 + c) * L1 + 4 * l];
    float sc = ssc, sh = ssh;
    float a[7];
#pragma unroll
    for (int i = 0; i < 7; i++) a[i] = fmaxf(0.f, fmaf(cr[i], sc, sh));
    float xf0 = fmaxf(fmaxf(a[0], a[1]), a[2]);
    float xf1 = fmaxf(fmaxf(a[2], a[3]), a[4]);
    float xf2 = fmaxf(fmaxf(a[4], a[5]), a[6]);
    float a_p = ap[c], b_p = bp[c], a_n = an[c], b_n = bn[c];
    float mp = fmaxf(fmaxf(sigfast(a_p * (xf0 - b_p)), sigfast(a_p * (xf1 - b_p))),
                     sigfast(a_p * (xf2 - b_p)));
    float mn = fmaxf(fmaxf(sigfast(-a_n * (xf0 - b_n)), sigfast(-a_n * (xf1 - b_n))),
                     sigfast(-a_n * (xf2 - b_n)));
    g_xmiu[(b * CM + c) * L3 + l] = mp;
    g_xmiu[(b * CM + 16 + c) * L3 + l] = mn;
}

// ---------------- entire autoencoder in one kernel (512 threads / batch) ----------------
// smem floats: sW 6144 | sA 5709 | sB 11115 (91.9KB)
#define AE_NTH 512
__global__ void k_ae_all(const float* __restrict__ xmiu,
                         const float* __restrict__ w1, const float* __restrict__ b1,
                         const float* __restrict__ w2, const float* __restrict__ b2,
                         const float* __restrict__ w3, const float* __restrict__ b3,
                         const float* __restrict__ w4, const float* __restrict__ b4,
                         float* __restrict__ h4g) {
    extern __shared__ float sm[];
    float* sW = sm;
    float* sA = sm + 6144;
    float* sB = sm + 6144 + 5709;
    const int OFF2 = 8192;
    int b = blockIdx.x, tid = threadIdx.x;

    // S0: W1 + x staging (rows 0..172, stride 33)
    for (int i = tid; i < 6144; i += AE_NTH) {
        int oc = i / 96, r = i % 96, ic = r / 3, kw = r % 3;
        sW[(kw * 32 + ic) * 64 + oc] = w1[i];
    }
    for (int i = tid; i < 173 * 32; i += AE_NTH) {
        int r = i / 32, ic = i % 32, l = r - 1;
        sA[r * 33 + ic] = (l >= 0 && l < L3) ? xmiu[(b * 32 + ic) * L3 + l] : 0.f;
    }
    __syncthreads();

    // S1: conv1(k3,pad1)+tanh -> T1 in sB (171 rows, stride 65); TM=6 single pass (16*29=464)
    for (int it = tid; it < 16 * 29; it += AE_NTH) {
        int og = it % 16, lg = it / 16, l0 = lg * 6;
        float acc[6][4] = {};
#pragma unroll 4
        for (int ic = 0; ic < 32; ic++) {
            float a[8];
#pragma unroll
            for (int r = 0; r < 8; r++) a[r] = sA[min(l0 + r, 172) * 33 + ic];
#pragma unroll
            for (int kw = 0; kw < 3; kw++) {
                float4 wv = *reinterpret_cast<const float4*>(&sW[(kw * 32 + ic) * 64 + og * 4]);
#pragma unroll
                for (int i = 0; i < 6; i++) {
                    float av = a[i + kw];
                    acc[i][0] = fmaf(av, wv.x, acc[i][0]);
                    acc[i][1] = fmaf(av, wv.y, acc[i][1]);
                    acc[i][2] = fmaf(av, wv.z, acc[i][2]);
                    acc[i][3] = fmaf(av, wv.w, acc[i][3]);
                }
            }
        }
#pragma unroll
        for (int i = 0; i < 6; i++) {
            int l = l0 + i;
            if (l < L3)
#pragma unroll
                for (int j = 0; j < 4; j++)
                    sB[l * 65 + og * 4 + j] = tanhf(acc[i][j] + __ldg(b1 + og * 4 + j));
        }
    }
    __syncthreads();

    // S2: W2 + pool(3,2) T1 -> h1 in sA (87 rows incl pads, stride 65)
    for (int i = tid; i < 6144; i += AE_NTH) {
        int oc = i / 192, r = i % 192, ic = r / 3, kw = r % 3;
        sW[(kw * 64 + ic) * 32 + oc] = w2[i];
    }
    for (int i = tid; i < 87 * 64; i += AE_NTH) {
        int r = i / 64, ic = i % 64, p = r - 1;
        float v = 0.f;
        if (p >= 0 && p < 85) {
            const float* t1 = &sB[(2 * p) * 65 + ic];
            v = fmaxf(fmaxf(t1[0], t1[65]), t1[130]);
        }
        sA[r * 65 + ic] = v;
    }
    __syncthreads();

    // S3: conv2(k3,pad1)+relu -> T2 in sB rows 0..84 (stride 33); TM=4, float2 weights, act regs
    for (int it = tid; it < 16 * 22; it += AE_NTH) {
        int og = it % 16, pg = it / 16, p0 = pg * 4;
        float acc[4][2] = {};
#pragma unroll 4
        for (int ic = 0; ic < 64; ic++) {
            float a[6];
#pragma unroll
            for (int r = 0; r < 6; r++) a[r] = sA[min(p0 + r, 86) * 65 + ic];
#pragma unroll
            for (int kw = 0; kw < 3; kw++) {
                float2 wv = *reinterpret_cast<const float2*>(&sW[(kw * 64 + ic) * 32 + og * 2]);
#pragma unroll
                for (int i = 0; i < 4; i++) {
                    float av = a[i + kw];
                    acc[i][0] = fmaf(av, wv.x, acc[i][0]);
                    acc[i][1] = fmaf(av, wv.y, acc[i][1]);
                }
            }
        }
#pragma unroll
        for (int i = 0; i < 4; i++) {
            int p = p0 + i;
            if (p < 85)
#pragma unroll
                for (int j = 0; j < 2; j++)
                    sB[p * 33 + og * 2 + j] = fmaxf(0.f, acc[i][j] + __ldg(b2 + og * 2 + j));
        }
    }
    __syncthreads();

    // S4: W3 + pool(3,2) T2 -> h2 at sB[OFF2] (42 rows, stride 33)
    for (int i = tid; i < 6144; i += AE_NTH) {
        int oc = i / 96, r = i % 96, ic = r / 3, kw = r % 3;
        sW[(kw * 32 + ic) * 64 + oc] = w3[i];
    }
    for (int i = tid; i < 42 * 32; i += AE_NTH) {
        int j = i / 32, ic = i % 32;
        const float* t2 = &sB[(2 * j) * 33 + ic];
        sB[OFF2 + j * 33 + ic] = fmaxf(fmaxf(t2[0], t2[33]), t2[66]);
    }
    __syncthreads();

    // S5: up2(h2) -> conv3(k3,pad2)+tanh -> h3 in sA (86 rows, stride 65); TM=4, up-gathers hoisted
    for (int it = tid; it < 352; it += AE_NTH) {
        int og = it % 16, tg = it / 16, t0 = tg * 4;
        float acc[4][4] = {};
#pragma unroll 4
        for (int ic = 0; ic < 32; ic++) {
            float a[7];
#pragma unroll
            for (int r = 0; r < 7; r++) {
                int u = t0 - 2 + r;
                float av = 0.f;
                if (u >= 0 && u < 84) {
                    int j = u >> 1;
                    int ja, jb; float wa, wb;
                    if (u & 1) { ja = j; jb = (j < 41) ? j + 1 : 41; wa = 0.75f; wb = 0.25f; }
                    else       { ja = (j > 0) ? j - 1 : 0; jb = j;  wa = 0.25f; wb = 0.75f; }
                    av = wa * sB[OFF2 + ja * 33 + ic] + wb * sB[OFF2 + jb * 33 + ic];
                }
                a[r] = av;
            }
#pragma unroll
            for (int kw = 0; kw < 3; kw++) {
                float4 wv = *reinterpret_cast<const float4*>(&sW[(kw * 32 + ic) * 64 + og * 4]);
#pragma unroll
                for (int i = 0; i < 4; i++) {
                    float av = a[i + kw];
                    acc[i][0] = fmaf(av, wv.x, acc[i][0]);
                    acc[i][1] = fmaf(av, wv.y, acc[i][1]);
                    acc[i][2] = fmaf(av, wv.z, acc[i][2]);
                    acc[i][3] = fmaf(av, wv.w, acc[i][3]);
                }
            }
        }
#pragma unroll
        for (int i = 0; i < 4; i++) {
            int t = t0 + i;
            if (t < 86)
#pragma unroll
                for (int j = 0; j < 4; j++)
                    sA[t * 65 + og * 4 + j] = tanhf(acc[i][j] + __ldg(b3 + og * 4 + j));
        }
    }
    __syncthreads();

    // S6: W4
    for (int i = tid; i < 6144; i += AE_NTH) {
        int oc = i / 192, r = i % 192, ic = r / 3, kw = r % 3;
        sW[(kw * 64 + ic) * 32 + oc] = w4[i];
    }
    __syncthreads();

    // S7: up2(h3) -> conv4(k3,pad2)+sigmoid -> h4 GLOBAL channel-first; TM=4, up-gathers hoisted
    for (int it = tid; it < 352; it += AE_NTH) {
        int og = it % 8, tg = it / 8, t0 = tg * 4;
        float acc[4][4] = {};
#pragma unroll 4
        for (int ic = 0; ic < 64; ic++) {
            float a[7];
#pragma unroll
            for (int r = 0; r < 7; r++) {
                int u = t0 - 2 + r;
                float av = 0.f;
                if (u >= 0 && u < 172) {
                    int j = u >> 1;
                    int ja, jb; float wa, wb;
                    if (u & 1) { ja = j; jb = (j < 85) ? j + 1 : 85; wa = 0.75f; wb = 0.25f; }
                    else       { ja = (j > 0) ? j - 1 : 0; jb = j;  wa = 0.25f; wb = 0.75f; }
                    av = wa * sA[ja * 65 + ic] + wb * sA[jb * 65 + ic];
                }
                a[r] = av;
            }
#pragma unroll
            for (int kw = 0; kw < 3; kw++) {
                float4 wv = *reinterpret_cast<const float4*>(&sW[(kw * 64 + ic) * 32 + og * 4]);
#pragma unroll
                for (int i = 0; i < 4; i++) {
                    float av = a[i + kw];
                    acc[i][0] = fmaf(av, wv.x, acc[i][0]);
                    acc[i][1] = fmaf(av, wv.y, acc[i][1]);
                    acc[i][2] = fmaf(av, wv.z, acc[i][2]);
                    acc[i][3] = fmaf(av, wv.w, acc[i][3]);
                }
            }
        }
#pragma unroll
        for (int i = 0; i < 4; i++) {
            int t = t0 + i;
            if (t < L9)
#pragma unroll
                for (int j = 0; j < 4; j++)
                    h4g[(b * 32 + og * 4 + j) * L9 + t] =
                        sigfast(acc[i][j] + __ldg(b4 + og * 4 + j));
        }
    }
}

// ---------------- softmax of logic weights + odd-tap sums ----------------
__global__ void k_softmax_all(const float* __restrict__ and2_w, const float* __restrict__ or2_w,
                              const float* __restrict__ and_w, const float* __restrict__ or_w) {
    int blk = blockIdx.x;
    const float* src; float* dst; int sz, o; float* s1dst = nullptr;
    if (blk < 20)      { src = and2_w; dst = g_wn_and2; sz = 320; o = blk; }
    else if (blk < 40) { src = or2_w;  dst = g_wn_or2;  sz = 320; o = blk - 20; }
    else if (blk < 46) { src = and_w;  dst = g_wn_and;  sz = 400; o = blk - 40; s1dst = g_s1_and; }
    else               { src = or_w;   dst = g_wn_or;   sz = 400; o = blk - 46; s1dst = g_s1_or; }
    const float* row = src + o * sz;
    int tid = threadIdx.x;
    __shared__ float red[64];
    float mx = -INFINITY;
    for (int i = tid; i < sz; i += 64) mx = fmaxf(mx, row[i]);
    red[tid] = mx; __syncthreads();
    for (int s = 32; s > 0; s >>= 1) { if (tid < s) red[tid] = fmaxf(red[tid], red[tid + s]); __syncthreads(); }
    mx = red[0]; __syncthreads();
    float sm = 0.f;
    for (int i = tid; i < sz; i += 64) sm += expf(row[i] - mx);
    red[tid] = sm; __syncthreads();
    for (int s = 32; s > 0; s >>= 1) { if (tid < s) red[tid] += red[tid + s]; __syncthreads(); }
    sm = red[0]; __syncthreads();
    float sodd = 0.f;
    for (int i = tid; i < sz; i += 64) {
        float v = expf(row[i] - mx) / sm;
        dst[o * sz + i] = v;
        if (i & 1) sodd += v;
    }
    if (s1dst) {
        red[tid] = sodd; __syncthreads();
        for (int s = 32; s > 0; s >>= 1) { if (tid < s) red[tid] += red[tid + s]; __syncthreads(); }
        if (tid == 0) s1dst[o] = red[0];
    }
}

// ---------------- logic layer 1 ----------------
__global__ void k_logic1() {
    __shared__ float2 sw2[20 * CI];
    int tid = threadIdx.x;
    int type = blockIdx.y;
    const float2* wsrc = reinterpret_cast<const float2*>(type == 0 ? g_wn_and2 : g_wn_or2);
    for (int i = tid; i < 20 * CI; i += 128) sw2[i] = wsrc[i];
    __syncthreads();
    int idx = blockIdx.x * 128 + tid;
    if (idx >= B * LU) return;
    int t = idx % LU, b = idx / LU;
    float base = (type == 0) ? LOGEPS : LOG1PE;
    float acc[20];
#pragma unroll
    for (int o = 0; o < 20; o++) acc[o] = base;
    for (int c = 0; c < 32; c++) {
        const float* h4p = &g_h4[(b * 32 + c) * L9 + t];
        float h0 = h4p[0], h1 = h4p[1], h2 = h4p[2], h3 = h4p[3], h4v = h4p[4];
        float wv0 = fmaxf(fmaxf(h0, h1), fmaxf(h2, h3));
        float wv1 = fmaxf(fmaxf(h1, h2), fmaxf(h3, h4v));
        const float* xmp = &g_xmiu[(b * 32 + c) * L3 + t];
        float p0 = wv0 * xmp[0], p1 = wv1 * xmp[1];
        int ch0 = binof(wv0) * 32 + c;
        int ch1 = binof(wv1) * 32 + c;
        float d0, d1;
        if (type == 0) {
            d0 = __logf(p0 + EPSL) - LOGEPS;
            d1 = __logf(p1 + EPSL) - LOGEPS;
        } else {
            d0 = __logf(1.0f - p0 + EPSL) - LOG1PE;
            d1 = __logf(1.0f - p1 + EPSL) - LOG1PE;
        }
#pragma unroll
        for (int o = 0; o < 20; o++) {
            acc[o] = fmaf(sw2[o * CI + ch0].x, d0, acc[o]);
            acc[o] = fmaf(sw2[o * CI + ch1].y, d1, acc[o]);
        }
    }
    float* x1 = &g_x1[(b * 40 + (type == 0 ? 0 : 20)) * LU + t];
    if (type == 0) {
#pragma unroll
        for (int o = 0; o < 20; o++) x1[o * LU] = fmaxf(0.f, __expf(acc[o]));
    } else {
#pragma unroll
        for (int o = 0; o < 20; o++) x1[o * LU] = fmaxf(0.f, 1.0f - __expf(acc[o]));
    }
}

// ---------------- logic layer 2 ----------------
__global__ void k_logic2() {
    __shared__ float2 swa2[6 * 200];
    __shared__ float2 swo2[6 * 200];
    int tid = threadIdx.x;
    const float2* wa = reinterpret_cast<const float2*>(g_wn_and);
    const float2* wo = reinterpret_cast<const float2*>(g_wn_or);
    for (int i = tid; i < 6 * 200; i += 128) { swa2[i] = wa[i]; swo2[i] = wo[i]; }
    __syncthreads();
    int idx = blockIdx.x * 128 + tid;
    if (idx >= B * LU) return;
    int t = idx % LU, b = idx / LU;
    bool hasL = (t > 0);
    float sa[6], so[6];
#pragma unroll
    for (int o = 0; o < 6; o++) {
        float fa = hasL ? 1.0f : g_s1_and[o];
        float fo = hasL ? 1.0f : g_s1_or[o];
        sa[o] = LOGEPS * fa;
        so[o] = LOG1PE * fo;
    }
    const float* xp = &g_x1[b * 40 * LU + t];
    for (int c = 0; c < 40; c++) {
        float v1 = xp[c * LU];
        float cv1 = fminf(fmaxf(v1, 0.f), 1.f);
        float d1p = __logf(cv1 + EPSL) - LOGEPS;
        float d1q = __logf(1.0f - cv1 + EPSL) - LOG1PE;
        float d0p = 0.f, d0q = 0.f;
        if (hasL) {
            float v0 = xp[c * LU - 1];
            float cv0 = fminf(fmaxf(v0, 0.f), 1.f);
            d0p = __logf(cv0 + EPSL) - LOGEPS;
            d0q = __logf(1.0f - cv0 + EPSL) - LOG1PE;
        }
#pragma unroll
        for (int o = 0; o < 6; o++) {
            float2 a2 = swa2[o * 200 + c];
            float2 o2 = swo2[o * 200 + c];
            sa[o] = fmaf(a2.y, d1p, sa[o]);
            so[o] = fmaf(o2.y, d1q, so[o]);
            if (hasL) {
                sa[o] = fmaf(a2.x, d0p, sa[o]);
                so[o] = fmaf(o2.x, d0q, so[o]);
            }
        }
    }
    for (int c = 0; c < 32; c++) {
        const float* h4p = &g_h4[(b * 32 + c) * L9 + t];
        const float* xmp = &g_xmiu[(b * 32 + c) * L3 + t];
        float h0 = h4p[0], h1 = h4p[1], h2 = h4p[2], h3 = h4p[3], h4v = h4p[4];
        float wv0 = fmaxf(fmaxf(h0, h1), fmaxf(h2, h3));
        float wv1 = fmaxf(fmaxf(h1, h2), fmaxf(h3, h4v));
        float p_0 = wv0 * xmp[0], p_1 = wv1 * xmp[1];
        int k0 = binof(wv0), k1 = binof(wv1);
        if (k0 == k1) {
            int ch = 40 + k0 * 32 + c;
            float u = fminf(p_0, p_1);
            float dp = __logf(u + EPSL) - LOGEPS;
            float dq = __logf(1.0f - u + EPSL) - LOG1PE;
#pragma unroll
            for (int o = 0; o < 6; o++) {
                sa[o] = fmaf(swa2[o * 200 + ch].y, dp, sa[o]);
                so[o] = fmaf(swo2[o * 200 + ch].y, dq, so[o]);
            }
        }
        if (hasL) {
            float hm1 = h4p[-1];
            float wvm = fmaxf(fmaxf(hm1, h0), fmaxf(h1, h2));
            float p_m = wvm * xmp[-1];
            int km = binof(wvm);
            if (km == k0) {
                int ch = 40 + km * 32 + c;
                float u = fminf(p_m, p_0);
                float dp = __logf(u + EPSL) - LOGEPS;
                float dq = __logf(1.0f - u + EPSL) - LOG1PE;
#pragma unroll
                for (int o = 0; o < 6; o++) {
                    sa[o] = fmaf(swa2[o * 200 + ch].x, dp, sa[o]);
                    so[o] = fmaf(swo2[o * 200 + ch].x, dq, so[o]);
                }
            }
        }
    }
#pragma unroll
    for (int o = 0; o < 6; o++) {
        g_x2[(b * 12 + o) * LU + t] = fmaxf(0.f, __expf(sa[o]));
        g_x2[(b * 12 + 6 + o) * LU + t] = fmaxf(0.f, 1.0f - __expf(so[o]));
    }
}

// ---------------- FC GEMM (64x64x16, 4x4, 256 thr) — fc1 ----------------
__global__ void k_gemm64(const float* __restrict__ A, const float* __restrict__ W,
                         const float* __restrict__ bias, float* __restrict__ C,
                         int M, int N, int K, int relu) {
    __shared__ float As[16][68];
    __shared__ float Bs[16][68];
    int tid = threadIdx.x;
    int tx = tid % 16, ty = tid / 16;
    int m0 = blockIdx.y * 64, n0 = blockIdx.x * 64;
    float acc[4][4] = {};
    for (int k0 = 0; k0 < K; k0 += 16) {
        int gk = k0 + tx;
        bool kv = (gk < K);
#pragma unroll
        for (int i = 0; i < 4; i++) {
            int r = ty + i * 16;
            int gm = m0 + r;
            As[tx][r] = (kv && gm < M) ? A[gm * K + gk] : 0.f;
            int gn = n0 + r;
            Bs[tx][r] = (kv && gn < N) ? W[gn * K + gk] : 0.f;
        }
        __syncthreads();
#pragma unroll
        for (int kk = 0; kk < 16; kk++) {
            float4 a = *reinterpret_cast<const float4*>(&As[kk][ty * 4]);
            float4 bq = *reinterpret_cast<const float4*>(&Bs[kk][tx * 4]);
            float av[4] = {a.x, a.y, a.z, a.w};
            float bv[4] = {bq.x, bq.y, bq.z, bq.w};
#pragma unroll
            for (int i = 0; i < 4; i++)
#pragma unroll
                for (int j = 0; j < 4; j++)
                    acc[i][j] = fmaf(av[i], bv[j], acc[i][j]);
        }
        __syncthreads();
    }
#pragma unroll
    for (int i = 0; i < 4; i++) {
        int gm = m0 + ty * 4 + i;
        if (gm >= M) continue;
#pragma unroll
        for (int j = 0; j < 4; j++) {
            int gn = n0 + tx * 4 + j;
            if (gn >= N) continue;
            float v = acc[i][j] + bias[gn];
            if (relu) v = fmaxf(v, 0.f);
            C[gm * N + gn] = v;
        }
    }
}

// ---------------- fc2 K-split: identical body, z selects K-half, raw partials ----------------
__global__ void k_gemm64_ks(const float* __restrict__ A, const float* __restrict__ W,
                            float* __restrict__ Cpart, int M, int N) {
    __shared__ float As[16][68];
    __shared__ float Bs[16][68];
    int tid = threadIdx.x;
    int tx = tid % 16, ty = tid / 16;
    int m0 = blockIdx.y * 64, n0 = blockIdx.x * 64;
    int kbeg = blockIdx.z * 512;
    const int K = 1024;
    float acc[4][4] = {};
    for (int k0 = kbeg; k0 < kbeg + 512; k0 += 16) {
        int gk = k0 + tx;
#pragma unroll
        for (int i = 0; i < 4; i++) {
            int r = ty + i * 16;
            int gm = m0 + r;
            As[tx][r] = (gm < M) ? A[gm * K + gk] : 0.f;
            int gn = n0 + r;
            Bs[tx][r] = (gn < N) ? W[gn * K + gk] : 0.f;
        }
        __syncthreads();
#pragma unroll
        for (int kk = 0; kk < 16; kk++) {
            float4 a = *reinterpret_cast<const float4*>(&As[kk][ty * 4]);
            float4 bq = *reinterpret_cast<const float4*>(&Bs[kk][tx * 4]);
            float av[4] = {a.x, a.y, a.z, a.w};
            float bv[4] = {bq.x, bq.y, bq.z, bq.w};
#pragma unroll
            for (int i = 0; i < 4; i++)
#pragma unroll
                for (int j = 0; j < 4; j++)
                    acc[i][j] = fmaf(av[i], bv[j], acc[i][j]);
        }
        __syncthreads();
    }
    float* Cz = Cpart + blockIdx.z * M * N;
#pragma unroll
    for (int i = 0; i < 4; i++) {
        int gm = m0 + ty * 4 + i;
        if (gm >= M) continue;
#pragma unroll
        for (int j = 0; j < 4; j++) {
            int gn = n0 + tx * 4 + j;
            if (gn >= N) continue;
            Cz[gm * N + gn] = acc[i][j];
        }
    }
}

// ---------------- fc3 with fused fc2 partial-sum + bias + relu ----------------
__global__ void k_fc3(const float* __restrict__ P, const float* __restrict__ b2,
                      const float* __restrict__ W, const float* __restrict__ bias,
                      float* __restrict__ C) {
    int idx = blockIdx.x * blockDim.x + threadIdx.x;
    if (idx >= B * 12 * 10) return;
    int m = idx / 10, n = idx % 10;
    const int MN = B * 12 * 256;
    float s = bias[n];
    const float* pa = P + m * 256;
    const float* pb = P + MN + m * 256;
    const float* w = W + n * 256;
#pragma unroll 8
    for (int k = 0; k < 256; k++) {
        float h = fmaxf(0.f, pa[k] + pb[k] + __ldg(b2 + k));
        s = fmaf(h, __ldg(w + k), s);
    }
    C[idx] = s;
}

// ---------------- launcher ----------------

extern "C" void kernel_launch(void* const* d_in, const int* in_sizes, int n_in,
                              void* d_out, int out_size) {
    const float* x      = (const float*)d_in[0];
    const float* wave_w = (const float*)d_in[1];
    const float* bn_g   = (const float*)d_in[2];
    const float* bn_b   = (const float*)d_in[3];
    const float* miu_ap = (const float*)d_in[4];
    const float* miu_bp = (const float*)d_in[5];
    const float* miu_an = (const float*)d_in[6];
    const float* miu_bn = (const float*)d_in[7];
    const float* ae_w1  = (const float*)d_in[8];
    const float* ae_b1  = (const float*)d_in[9];
    const float* ae_w2  = (const float*)d_in[10];
    const float* ae_b2  = (const float*)d_in[11];
    const float* ae_w3  = (const float*)d_in[12];
    const float* ae_b3  = (const float*)d_in[13];
    const float* ae_w4  = (const float*)d_in[14];
    const float* ae_b4  = (const float*)d_in[15];
    const float* and2_w = (const float*)d_in[16];
    const float* or2_w  = (const float*)d_in[17];
    const float* and_w  = (const float*)d_in[18];
    const float* or_w   = (const float*)d_in[19];
    const float* fc1_w  = (const float*)d_in[20];
    const float* fc1_b  = (const float*)d_in[21];
    const float* fc2_w  = (const float*)d_in[22];
    const float* fc2_b  = (const float*)d_in[23];
    const float* fc3_w  = (const float*)d_in[24];
    const float* fc3_b  = (const float*)d_in[25];
    float* out = (float*)d_out;

    float *pxmiu, *ph4, *px2, *pf1, *pf2p;
    cudaGetSymbolAddress((void**)&pxmiu, g_xmiu);
    cudaGetSymbolAddress((void**)&ph4, g_h4);
    cudaGetSymbolAddress((void**)&px2, g_x2);
    cudaGetSymbolAddress((void**)&pf1, g_fc1o);
    cudaGetSymbolAddress((void**)&pf2p, g_fc2p);

    const int AE_SMEM = (6144 + 5709 + 11115) * 4;
    cudaFuncSetAttribute(k_ae_all, cudaFuncAttributeMaxDynamicSharedMemorySize, AE_SMEM);

    k_softmax_all<<<52, 64>>>(and2_w, or2_w, and_w, or_w);
    k_conv1<<<dim3(C1, B), 256>>>(x, wave_w);
    k_front<<<dim3(C1, B), 192>>>(bn_g, bn_b, miu_ap, miu_bp, miu_an, miu_bn);
    k_ae_all<<<B, AE_NTH, AE_SMEM>>>(pxmiu, ae_w1, ae_b1, ae_w2, ae_b2,
                                     ae_w3, ae_b3, ae_w4, ae_b4, ph4);
    k_logic1<<<dim3(cdiv(B * LU, 128), 2), 128>>>();
    k_logic2<<<cdiv(B * LU, 128), 128>>>();
    k_gemm64<<<dim3(1024 / 64, (B * 12) / 64), 256>>>(px2, fc1_w, fc1_b, pf1, B * 12, 1024, LU, 1);
    k_gemm64_ks<<<dim3(256 / 64, (B * 12) / 64, 2), 256>>>(pf1, fc2_w, pf2p, B * 12, 256);
    k_fc3<<<cdiv(B * 12 * 10, 256), 256>>>(pf2p, fc2_b, fc3_w, fc3_b, out);

    (void)in_sizes; (void)n_in; (void)out_size;
}